// round 13
// baseline (speedup 1.0000x reference)
#include <cuda_runtime.h>
#include <cuda_fp16.h>
#include <cstdint>

#define D        256
#define K        1024
#define HW       1024
#define NBLK     256
#define IDX_OFF  8388608
#define LOSS_OFF 8421376
#define MARGIN   0.12f

// smem layout (bytes)
#define OFF_A    0          // 128 x 264 halves = 67584 ; reused as output stage [32][260] f32
#define OFF_B    67584      // 2 bufs x 16896 (32 codes x 528B); reused as sz for deep scan
#define BBUF_SZ  16896
#define OFF_CN   101376     // 4096
#define OFF_STG  105472     // 256 x float4 = 4096
#define OFF_V3   109568     // 256 x float = 1024
#define OFF_ROW  110592     // 128 x int = 512
#define OFF_PT   111104     // pair tok, 128 x int
#define OFF_PC   111616     // pair codes, 128 x int2 = 1024
#define OFF_DP   112640     // deep tok, 128 x int
#define OFF_CNT  113152     // [0] pairCnt, [1] deepCnt; sbest @ +8; wsum @ +16
#define SMEM_SZ  113280

__device__ float    g_cnorm[K];
__device__ float    g_partial[NBLK];
__device__ uint16_t g_cbf16[K * D];

// ---------------- helpers ----------------
__device__ __forceinline__ uint32_t smem_u32(const void* p) {
    uint32_t a;
    asm("{ .reg .u64 t; cvta.to.shared.u64 t, %1; cvt.u32.u64 %0, t; }" : "=r"(a) : "l"(p));
    return a;
}
#define CP_ASYNC16(dst, src) \
    asm volatile("cp.async.cg.shared.global [%0], [%1], 16;" :: "r"(dst), "l"(src) : "memory")
#define CP_COMMIT() asm volatile("cp.async.commit_group;" ::: "memory")
#define CP_WAIT0()  asm volatile("cp.async.wait_group 0;" ::: "memory")

__device__ __forceinline__ void ldsm_x4(uint32_t* r, uint32_t a) {
    asm volatile("ldmatrix.sync.aligned.m8n8.x4.shared.b16 {%0,%1,%2,%3}, [%4];"
        : "=r"(r[0]), "=r"(r[1]), "=r"(r[2]), "=r"(r[3]) : "r"(a));
}
__device__ __forceinline__ void mma_fp16(float* c, const uint32_t* a, const uint32_t* b) {
    asm volatile(
        "mma.sync.aligned.m16n8k16.row.col.f32.f16.f16.f32 "
        "{%0,%1,%2,%3}, {%4,%5,%6,%7}, {%8,%9}, {%0,%1,%2,%3};"
        : "+f"(c[0]), "+f"(c[1]), "+f"(c[2]), "+f"(c[3])
        : "r"(a[0]), "r"(a[1]), "r"(a[2]), "r"(a[3]), "r"(b[0]), "r"(b[1]));
}
// exact tie rule (used only in rescue paths)
__device__ __forceinline__ bool better(float v, int i, float V, int I) {
    return v < V || (v == V && i < I);
}
// strict-< branchless insert; ties fall out as gap==0 -> flagged -> exact rescue
__device__ __forceinline__ void ins2v3(float v, int i,
                                       float& v1, int& i1, float& v2, int& i2, float& v3) {
    bool lt2 = v < v2;
    bool lt1 = v < v1;
    v3 = lt2 ? v2 : fminf(v3, v);
    float nv2 = lt1 ? v1 : v;  int ni2 = lt1 ? i1 : i;
    v2 = lt2 ? nv2 : v2;       i2 = lt2 ? ni2 : i2;
    v1 = lt1 ? v : v1;         i1 = lt1 ? i : i1;
}
__device__ __forceinline__ uint32_t fkey(float f) {
    uint32_t u = __float_as_uint(f);
    return (u & 0x80000000u) ? ~u : (u | 0x80000000u);
}

// ---------------- Kernel 0: codebook -> fp16 + cnorm (fused) ----------------
__global__ __launch_bounds__(256) void prepcn_kernel(const float* __restrict__ cb) {
    __shared__ float ws[8];
    const int r = blockIdx.x, t = threadIdx.x;
    float v = cb[r * D + t];
    g_cbf16[r * D + t] = __half_as_ushort(__float2half(v));
    float s = v * v;
#pragma unroll
    for (int o = 16; o; o >>= 1) s += __shfl_xor_sync(~0u, s, o);
    if ((t & 31) == 0) ws[t >> 5] = s;
    __syncthreads();
    if (t == 0) {
        float tot = 0.f;
#pragma unroll
        for (int i = 0; i < 8; i++) tot += ws[i];
        g_cnorm[r] = tot;
    }
}

// ---------------- Kernel 1: fused GEMM + argmin + rescue + outputs ----------------
__global__ __launch_bounds__(256, 2) void vq_main(const float* __restrict__ z,
                                                  const float* __restrict__ cb,
                                                  float* __restrict__ out) {
    extern __shared__ char sm[];
    const uint32_t su = smem_u32(sm);
    const int t = threadIdx.x, w = t >> 5, lane = t & 31;
    const int g = lane >> 2, p = lane & 3;
    const int mw = w >> 1, nw = w & 1;
    const int n0 = blockIdx.x * 128;
    const int b = n0 >> 10, hw0 = n0 & 1023;
    const float* zb = z + b * (D * HW) + hw0;

    uint16_t* sA   = (uint16_t*)(sm + OFF_A);
    float*    scn  = (float*)(sm + OFF_CN);
    float4*   stg  = (float4*)(sm + OFF_STG);
    float*    sv3  = (float*)(sm + OFF_V3);
    int*      sRow = (int*)(sm + OFF_ROW);
    int*      sPT  = (int*)(sm + OFF_PT);
    int2*     sPC  = (int2*)(sm + OFF_PC);
    int*      sDP  = (int*)(sm + OFF_DP);
    int*      sCnt = (int*)(sm + OFF_CNT);
    unsigned long long* sBest = (unsigned long long*)(sm + OFF_CNT + 8);
    float*    wsum = (float*)(sm + OFF_CNT + 16);

    if (t == 0) { sCnt[0] = 0; sCnt[1] = 0; }

    // ---- A: load z coalesced -> fp16 smem [tok][dim] ----
#pragma unroll
    for (int j = 0; j < 32; j++) {
        int l = j * 256 + t;
        int d = l >> 5, f4 = l & 31;
        float4 v = *(const float4*)(zb + d * HW + f4 * 4);
        float vv[4] = {v.x, v.y, v.z, v.w};
#pragma unroll
        for (int q = 0; q < 4; q++)
            sA[(f4 * 4 + q) * 264 + d] = __half_as_ushort(__float2half(vv[q]));
    }
    for (int c = t; c < K; c += 256) scn[c] = g_cnorm[c];

    // prefetch B chunk 0
#pragma unroll
    for (int j = 0; j < 4; j++) {
        int s = j * 256 + t;
        int code = s >> 5, seg = s & 31;
        CP_ASYNC16(su + OFF_B + code * 528 + seg * 16,
                   (const char*)g_cbf16 + code * 512 + seg * 16);
    }
    CP_COMMIT();

    const int l8 = lane & 7, mat = lane >> 3;
    const uint32_t aAddr = su + OFF_A
        + (uint32_t)((mw * 32 + l8 + (mat & 1) * 8) * 528 + (mat >> 1) * 16);
    const uint32_t boff = (uint32_t)((nw * 16 + (mat >> 1) * 8 + l8) * 528 + (mat & 1) * 16);

    float rv1[2][2], rv2[2][2], rv3[2][2];
    int   ri1[2][2], ri2[2][2];
#pragma unroll
    for (int mt = 0; mt < 2; mt++)
#pragma unroll
        for (int rr = 0; rr < 2; rr++) {
            rv1[mt][rr] = 3.4e38f; rv2[mt][rr] = 3.4e38f; rv3[mt][rr] = 3.4e38f;
            ri1[mt][rr] = 0; ri2[mt][rr] = 0;
        }

    // double-banked accumulators: fold bank nc^1 while bank nc's MMAs run
    float accb[2][2][2][4];

    for (int nc = 0; nc < 32; nc++) {
        CP_WAIT0();
        __syncthreads();   // chunk nc visible; all warps done reading buffer (nc+1)&1

        if (nc < 31) {
            int nn = nc + 1, buf = nn & 1;
#pragma unroll
            for (int j = 0; j < 4; j++) {
                int s = j * 256 + t;
                int code = s >> 5, seg = s & 31;
                CP_ASYNC16(su + OFF_B + buf * BBUF_SZ + code * 528 + seg * 16,
                           (const char*)g_cbf16 + (nn * 32 + code) * 512 + seg * 16);
            }
            CP_COMMIT();
        }

        const int bank = nc & 1;
        const uint32_t bAddr = su + OFF_B + (uint32_t)bank * BBUF_SZ + boff;

#pragma unroll
        for (int mt = 0; mt < 2; mt++)
#pragma unroll
            for (int nt = 0; nt < 2; nt++)
#pragma unroll
                for (int q = 0; q < 4; q++) accb[bank][mt][nt][q] = 0.f;

        uint32_t ah[2][2][4], bb[2][4];
        ldsm_x4(ah[0][0], aAddr);
        ldsm_x4(ah[0][1], aAddr + 16 * 528);
        ldsm_x4(bb[0], bAddr);

#pragma unroll
        for (int ks = 0; ks < 16; ks++) {
            const int cur = ks & 1, nxt = cur ^ 1;
            if (ks < 15) {
                uint32_t ko = (uint32_t)((ks + 1) * 32);
                ldsm_x4(ah[nxt][0], aAddr + ko);
                ldsm_x4(ah[nxt][1], aAddr + 16 * 528 + ko);
                ldsm_x4(bb[nxt], bAddr + ko);
            }
#pragma unroll
            for (int mt = 0; mt < 2; mt++)
#pragma unroll
                for (int nt = 0; nt < 2; nt++)
                    mma_fp16(accb[bank][mt][nt], ah[cur][mt], &bb[cur][nt * 2]);
        }

        // deferred fold: previous chunk's bank (no dependency on in-flight MMAs)
        if (nc > 0) {
            const int pb = bank ^ 1, pc0 = (nc - 1) * 32;
#pragma unroll
            for (int nt = 0; nt < 2; nt++)
#pragma unroll
                for (int q = 0; q < 2; q++) {
                    int c = pc0 + nw * 16 + nt * 8 + 2 * p + q;
                    float cn = scn[c];
#pragma unroll
                    for (int mt = 0; mt < 2; mt++)
#pragma unroll
                        for (int rr = 0; rr < 2; rr++) {
                            float v = fmaf(-2.f, accb[pb][mt][nt][rr * 2 + q], cn);
                            ins2v3(v, c, rv1[mt][rr], ri1[mt][rr],
                                   rv2[mt][rr], ri2[mt][rr], rv3[mt][rr]);
                        }
                }
        }
    }
    // fold last chunk (bank 1, chunk 31)
    {
        const int pc0 = 31 * 32;
#pragma unroll
        for (int nt = 0; nt < 2; nt++)
#pragma unroll
            for (int q = 0; q < 2; q++) {
                int c = pc0 + nw * 16 + nt * 8 + 2 * p + q;
                float cn = scn[c];
#pragma unroll
                for (int mt = 0; mt < 2; mt++)
#pragma unroll
                    for (int rr = 0; rr < 2; rr++) {
                        float v = fmaf(-2.f, accb[1][mt][nt][rr * 2 + q], cn);
                        ins2v3(v, c, rv1[mt][rr], ri1[mt][rr],
                               rv2[mt][rr], ri2[mt][rr], rv3[mt][rr]);
                    }
            }
    }

    // ---- merge across p lanes (xor 1, 2) ----
#pragma unroll
    for (int o = 1; o <= 2; o <<= 1) {
#pragma unroll
        for (int mt = 0; mt < 2; mt++)
#pragma unroll
            for (int rr = 0; rr < 2; rr++) {
                float ov1 = __shfl_xor_sync(~0u, rv1[mt][rr], o);
                int   oi1 = __shfl_xor_sync(~0u, ri1[mt][rr], o);
                float ov2 = __shfl_xor_sync(~0u, rv2[mt][rr], o);
                int   oi2 = __shfl_xor_sync(~0u, ri2[mt][rr], o);
                float ov3 = __shfl_xor_sync(~0u, rv3[mt][rr], o);
                ins2v3(ov1, oi1, rv1[mt][rr], ri1[mt][rr],
                       rv2[mt][rr], ri2[mt][rr], rv3[mt][rr]);
                ins2v3(ov2, oi2, rv1[mt][rr], ri1[mt][rr],
                       rv2[mt][rr], ri2[mt][rr], rv3[mt][rr]);
                rv3[mt][rr] = fminf(rv3[mt][rr], ov3);
            }
    }
    if (p == 0) {
#pragma unroll
        for (int mt = 0; mt < 2; mt++)
#pragma unroll
            for (int rr = 0; rr < 2; rr++) {
                int tok = mw * 32 + mt * 16 + rr * 8 + g;
                stg[tok * 2 + nw] = make_float4(rv1[mt][rr], __int_as_float(ri1[mt][rr]),
                                                rv2[mt][rr], __int_as_float(ri2[mt][rr]));
                sv3[tok * 2 + nw] = rv3[mt][rr];
            }
    }
    __syncthreads();

    // ---- per-token final merge + flag ----
    if (t < 128) {
        float4 a0 = stg[t * 2 + 0];
        float4 b0 = stg[t * 2 + 1];
        float fv1 = a0.x, fv2 = a0.z, fv3 = sv3[t * 2 + 0];
        int   fi1 = __float_as_int(a0.y), fi2 = __float_as_int(a0.w);
        ins2v3(b0.x, __float_as_int(b0.y), fv1, fi1, fv2, fi2, fv3);
        ins2v3(b0.z, __float_as_int(b0.w), fv1, fi1, fv2, fi2, fv3);
        fv3 = fminf(fv3, sv3[t * 2 + 1]);
        sRow[t] = fi1;
        if (fv3 - fv1 < MARGIN) {
            int s = atomicAdd(&sCnt[1], 1);
            sDP[s] = t;
        } else if (fv2 - fv1 < MARGIN) {
            int s = atomicAdd(&sCnt[0], 1);
            sPT[s] = t;
            sPC[s] = make_int2(fi1, fi2);
        }
    }
    __syncthreads();

    // ---- in-block exact fp32 pair rescore (one warp per flagged token) ----
    const int pairCnt = sCnt[0], deepCnt = sCnt[1];
    for (int i = w; i < pairCnt; i += 8) {
        int tok = sPT[i]; int2 cc = sPC[i];
        const float* zp = zb + tok;
        const float* p1 = cb + cc.x * D;
        const float* p2 = cb + cc.y * D;
        float zz = 0.f, d1 = 0.f, d2 = 0.f;
#pragma unroll
        for (int d = lane; d < D; d += 32) {
            float ze = zp[d * HW];
            zz = fmaf(ze, ze, zz);
            d1 = fmaf(ze, __ldg(p1 + d), d1);
            d2 = fmaf(ze, __ldg(p2 + d), d2);
        }
#pragma unroll
        for (int o = 16; o; o >>= 1) {
            zz += __shfl_xor_sync(~0u, zz, o);
            d1 += __shfl_xor_sync(~0u, d1, o);
            d2 += __shfl_xor_sync(~0u, d2, o);
        }
        if (lane == 0) {
            float D1 = __fadd_rn(__fsub_rn(zz, __fmul_rn(2.f, d1)), g_cnorm[cc.x]);
            float D2 = __fadd_rn(__fsub_rn(zz, __fmul_rn(2.f, d2)), g_cnorm[cc.y]);
            sRow[tok] = better(D2, cc.y, D1, cc.x) ? cc.y : cc.x;
        }
    }
    __syncthreads();

    // ---- in-block exact fp32 full scan for deep-doubt (rare) ----
    float* sz = (float*)(sm + OFF_B);
    for (int e = 0; e < deepCnt; e++) {
        int tok = sDP[e];
        sz[t] = zb[tok + t * HW];
        if (t == 0) *sBest = ~0ull;
        __syncthreads();
        const float4* szp = (const float4*)sz;
        float bv = 3.4e38f; int bi = 0;
#pragma unroll
        for (int j = 0; j < 4; j++) {
            int c = t + j * 256;
            const float4* row = (const float4*)(cb + c * D);
            float dsum = 0.f;
#pragma unroll 8
            for (int q = 0; q < 64; q++) {
                float4 zv = szp[q];
                float4 rv = __ldg(row + q);
                dsum = fmaf(zv.x, rv.x, dsum);
                dsum = fmaf(zv.y, rv.y, dsum);
                dsum = fmaf(zv.z, rv.z, dsum);
                dsum = fmaf(zv.w, rv.w, dsum);
            }
            float v = fmaf(-2.f, dsum, g_cnorm[c]);
            if (v < bv) { bv = v; bi = c; }
        }
        unsigned long long key = ((unsigned long long)fkey(bv) << 32) | (uint32_t)bi;
        atomicMin(sBest, key);
        __syncthreads();
        if (t == 0) sRow[tok] = (int)(*sBest & 0xffffffffu);
        __syncthreads();
    }

    // ---- outputs: indices, z_q_st via smem-staged coalesced gather, loss ----
    if (t < 128) out[IDX_OFF + n0 + t] = (float)sRow[t];

    float* stage = (float*)(sm + OFF_A);   // [32][260] f32 (reuses A panel space)
    float* outz = out + b * (D * HW) + hw0;
    float lsum = 0.f;
    for (int g4 = 0; g4 < 4; g4++) {
        const int i0 = g4 * 32;
        __syncthreads();     // stage safe to overwrite
#pragma unroll
        for (int j = 0; j < 8; j++) {
            int idx = j * 256 + t;
            int tl = idx >> 6, f4 = idx & 63;
            float4 v = __ldg((const float4*)(cb + sRow[i0 + tl] * D) + f4);
            *(float4*)(stage + tl * 260 + f4 * 4) = v;
        }
        __syncthreads();
#pragma unroll 8
        for (int j = 0; j < 32; j++) {
            int l = j * 256 + t;
            int d = l >> 5, i = l & 31;
            float ze = zb[d * HW + i0 + i];
            float zq = stage[i * 260 + d];
            float diff = zq - ze;
            outz[d * HW + i0 + i] = ze + diff;
            lsum = fmaf(diff, diff, lsum);
        }
    }
#pragma unroll
    for (int o = 16; o; o >>= 1) lsum += __shfl_xor_sync(~0u, lsum, o);
    if (lane == 0) wsum[w] = lsum;
    __syncthreads();
    if (t == 0) {
        float s = 0.f;
#pragma unroll
        for (int ww = 0; ww < 8; ww++) s += wsum[ww];
        g_partial[blockIdx.x] = s;
    }
}

// ---------------- Kernel 2: final loss ----------------
__global__ void finalize_kernel(float* __restrict__ out) {
    float s = 0.f;
    for (int i = 0; i < NBLK; i++) s += g_partial[i];
    float mean = s / 8388608.f;
    out[LOSS_OFF] = mean + 0.25f * mean;
}

// ---------------------------------------------------------------------------
extern "C" void kernel_launch(void* const* d_in, const int* in_sizes, int n_in,
                              void* d_out, int out_size) {
    const float* z  = (const float*)d_in[0];
    const float* cb = (const float*)d_in[1];
    float* out = (float*)d_out;

    cudaFuncSetAttribute(vq_main, cudaFuncAttributeMaxDynamicSharedMemorySize, SMEM_SZ);

    prepcn_kernel<<<K, 256>>>(cb);
    vq_main<<<NBLK, 256, SMEM_SZ>>>(z, cb, out);
    finalize_kernel<<<1, 1>>>(out);
}

// round 14
// speedup vs baseline: 1.1227x; 1.1227x over previous
#include <cuda_runtime.h>
#include <cuda_fp16.h>
#include <cstdint>

#define D        256
#define K        1024
#define HW       1024
#define NBLK     256
#define IDX_OFF  8388608
#define LOSS_OFF 8421376
#define MARGIN   0.12f

// smem layout (bytes)
#define OFF_A    0          // 128 x 264 halves = 67584 ; reused as output stage [32][260] f32
#define OFF_B    67584      // 2 bufs x 16896 (32 codes x 528B); reused as sz for deep scan
#define BBUF_SZ  16896
#define OFF_CN   101376     // 4096
#define OFF_STG  105472     // 256 x float4 = 4096
#define OFF_V3   109568     // 256 x float = 1024
#define OFF_ROW  110592     // 128 x int = 512
#define OFF_PT   111104     // pair tok, 128 x int
#define OFF_PC   111616     // pair codes, 128 x int2 = 1024
#define OFF_DP   112640     // deep tok, 128 x int
#define OFF_CNT  113152     // [0] pairCnt, [1] deepCnt; sbest @ +8; wsum @ +16
#define SMEM_SZ  113280

__device__ float    g_cnorm[K];
__device__ float    g_partial[NBLK];
__device__ uint16_t g_cbf16[K * D];

// ---------------- helpers ----------------
__device__ __forceinline__ uint32_t smem_u32(const void* p) {
    uint32_t a;
    asm("{ .reg .u64 t; cvta.to.shared.u64 t, %1; cvt.u32.u64 %0, t; }" : "=r"(a) : "l"(p));
    return a;
}
#define CP_ASYNC16(dst, src) \
    asm volatile("cp.async.cg.shared.global [%0], [%1], 16;" :: "r"(dst), "l"(src) : "memory")
#define CP_COMMIT() asm volatile("cp.async.commit_group;" ::: "memory")
#define CP_WAIT0()  asm volatile("cp.async.wait_group 0;" ::: "memory")

__device__ __forceinline__ void ldsm_x4(uint32_t* r, uint32_t a) {
    asm volatile("ldmatrix.sync.aligned.m8n8.x4.shared.b16 {%0,%1,%2,%3}, [%4];"
        : "=r"(r[0]), "=r"(r[1]), "=r"(r[2]), "=r"(r[3]) : "r"(a));
}
__device__ __forceinline__ void mma_fp16(float* c, const uint32_t* a, const uint32_t* b) {
    asm volatile(
        "mma.sync.aligned.m16n8k16.row.col.f32.f16.f16.f32 "
        "{%0,%1,%2,%3}, {%4,%5,%6,%7}, {%8,%9}, {%0,%1,%2,%3};"
        : "+f"(c[0]), "+f"(c[1]), "+f"(c[2]), "+f"(c[3])
        : "r"(a[0]), "r"(a[1]), "r"(a[2]), "r"(a[3]), "r"(b[0]), "r"(b[1]));
}
// exact tie rule (used only in rescue paths)
__device__ __forceinline__ bool better(float v, int i, float V, int I) {
    return v < V || (v == V && i < I);
}
// strict-< branchless insert; ties fall out as gap==0 -> flagged -> exact rescue
__device__ __forceinline__ void ins2v3(float v, int i,
                                       float& v1, int& i1, float& v2, int& i2, float& v3) {
    bool lt2 = v < v2;
    bool lt1 = v < v1;
    v3 = lt2 ? v2 : fminf(v3, v);
    float nv2 = lt1 ? v1 : v;  int ni2 = lt1 ? i1 : i;
    v2 = lt2 ? nv2 : v2;       i2 = lt2 ? ni2 : i2;
    v1 = lt1 ? v : v1;         i1 = lt1 ? i : i1;
}
__device__ __forceinline__ uint32_t fkey(float f) {
    uint32_t u = __float_as_uint(f);
    return (u & 0x80000000u) ? ~u : (u | 0x80000000u);
}

// ---------------- Kernel 0: codebook -> fp16 + cnorm (fused) ----------------
__global__ __launch_bounds__(256) void prepcn_kernel(const float* __restrict__ cb) {
    __shared__ float ws[8];
    const int r = blockIdx.x, t = threadIdx.x;
    float v = cb[r * D + t];
    g_cbf16[r * D + t] = __half_as_ushort(__float2half(v));
    float s = v * v;
#pragma unroll
    for (int o = 16; o; o >>= 1) s += __shfl_xor_sync(~0u, s, o);
    if ((t & 31) == 0) ws[t >> 5] = s;
    __syncthreads();
    if (t == 0) {
        float tot = 0.f;
#pragma unroll
        for (int i = 0; i < 8; i++) tot += ws[i];
        g_cnorm[r] = tot;
    }
}

// ---------------- Kernel 1: fused GEMM + argmin + rescue + outputs ----------------
__global__ __launch_bounds__(256, 2) void vq_main(const float* __restrict__ z,
                                                  const float* __restrict__ cb,
                                                  float* __restrict__ out) {
    extern __shared__ char sm[];
    const uint32_t su = smem_u32(sm);
    const int t = threadIdx.x, w = t >> 5, lane = t & 31;
    const int g = lane >> 2, p = lane & 3;
    const int mw = w >> 1, nw = w & 1;
    const int n0 = blockIdx.x * 128;
    const int b = n0 >> 10, hw0 = n0 & 1023;
    const float* zb = z + b * (D * HW) + hw0;

    uint16_t* sA   = (uint16_t*)(sm + OFF_A);
    float*    scn  = (float*)(sm + OFF_CN);
    float4*   stg  = (float4*)(sm + OFF_STG);
    float*    sv3  = (float*)(sm + OFF_V3);
    int*      sRow = (int*)(sm + OFF_ROW);
    int*      sPT  = (int*)(sm + OFF_PT);
    int2*     sPC  = (int2*)(sm + OFF_PC);
    int*      sDP  = (int*)(sm + OFF_DP);
    int*      sCnt = (int*)(sm + OFF_CNT);
    unsigned long long* sBest = (unsigned long long*)(sm + OFF_CNT + 8);
    float*    wsum = (float*)(sm + OFF_CNT + 16);

    if (t == 0) { sCnt[0] = 0; sCnt[1] = 0; }

    // ---- A: load z coalesced -> fp16 smem [tok][dim] ----
#pragma unroll
    for (int j = 0; j < 32; j++) {
        int l = j * 256 + t;
        int d = l >> 5, f4 = l & 31;
        float4 v = *(const float4*)(zb + d * HW + f4 * 4);
        float vv[4] = {v.x, v.y, v.z, v.w};
#pragma unroll
        for (int q = 0; q < 4; q++)
            sA[(f4 * 4 + q) * 264 + d] = __half_as_ushort(__float2half(vv[q]));
    }
    for (int c = t; c < K; c += 256) scn[c] = g_cnorm[c];

    // prefetch B chunk 0
#pragma unroll
    for (int j = 0; j < 4; j++) {
        int s = j * 256 + t;
        int code = s >> 5, seg = s & 31;
        CP_ASYNC16(su + OFF_B + code * 528 + seg * 16,
                   (const char*)g_cbf16 + code * 512 + seg * 16);
    }
    CP_COMMIT();

    const int l8 = lane & 7, mat = lane >> 3;
    const uint32_t aAddr = su + OFF_A
        + (uint32_t)((mw * 32 + l8 + (mat & 1) * 8) * 528 + (mat >> 1) * 16);
    const uint32_t boff = (uint32_t)((nw * 16 + (mat >> 1) * 8 + l8) * 528 + (mat & 1) * 16);

    float rv1[2][2], rv2[2][2], rv3[2][2];
    int   ri1[2][2], ri2[2][2];
#pragma unroll
    for (int mt = 0; mt < 2; mt++)
#pragma unroll
        for (int rr = 0; rr < 2; rr++) {
            rv1[mt][rr] = 3.4e38f; rv2[mt][rr] = 3.4e38f; rv3[mt][rr] = 3.4e38f;
            ri1[mt][rr] = 0; ri2[mt][rr] = 0;
        }

    for (int nc = 0; nc < 32; nc++) {
        CP_WAIT0();
        __syncthreads();   // chunk nc visible; all warps fully done with iter nc-1

        if (nc < 31) {
            int nn = nc + 1, buf = nn & 1;
#pragma unroll
            for (int j = 0; j < 4; j++) {
                int s = j * 256 + t;
                int code = s >> 5, seg = s & 31;
                CP_ASYNC16(su + OFF_B + buf * BBUF_SZ + code * 528 + seg * 16,
                           (const char*)g_cbf16 + (nn * 32 + code) * 512 + seg * 16);
            }
            CP_COMMIT();
        }

        const uint32_t bAddr = su + OFF_B + (uint32_t)(nc & 1) * BBUF_SZ + boff;

        float acc[2][2][4];
#pragma unroll
        for (int mt = 0; mt < 2; mt++)
#pragma unroll
            for (int nt = 0; nt < 2; nt++)
#pragma unroll
                for (int q = 0; q < 4; q++) acc[mt][nt][q] = 0.f;

        uint32_t ah[2][2][4], bb[2][4];
        ldsm_x4(ah[0][0], aAddr);
        ldsm_x4(ah[0][1], aAddr + 16 * 528);
        ldsm_x4(bb[0], bAddr);

#pragma unroll
        for (int ks = 0; ks < 16; ks++) {
            const int cur = ks & 1, nxt = cur ^ 1;
            if (ks < 15) {
                uint32_t ko = (uint32_t)((ks + 1) * 32);
                ldsm_x4(ah[nxt][0], aAddr + ko);
                ldsm_x4(ah[nxt][1], aAddr + 16 * 528 + ko);
                ldsm_x4(bb[nxt], bAddr + ko);
            }
#pragma unroll
            for (int mt = 0; mt < 2; mt++)
#pragma unroll
                for (int nt = 0; nt < 2; nt++)
                    mma_fp16(acc[mt][nt], ah[cur][mt], &bb[cur][nt * 2]);
        }

        // strict-< branchless fold; codes ascending per thread
#pragma unroll
        for (int nt = 0; nt < 2; nt++)
#pragma unroll
            for (int q = 0; q < 2; q++) {
                int c = nc * 32 + nw * 16 + nt * 8 + 2 * p + q;
                float cn = scn[c];
#pragma unroll
                for (int mt = 0; mt < 2; mt++)
#pragma unroll
                    for (int rr = 0; rr < 2; rr++) {
                        float v = fmaf(-2.f, acc[mt][nt][rr * 2 + q], cn);
                        ins2v3(v, c, rv1[mt][rr], ri1[mt][rr],
                               rv2[mt][rr], ri2[mt][rr], rv3[mt][rr]);
                    }
            }
    }

    // ---- merge across p lanes (xor 1, 2) ----
#pragma unroll
    for (int o = 1; o <= 2; o <<= 1) {
#pragma unroll
        for (int mt = 0; mt < 2; mt++)
#pragma unroll
            for (int rr = 0; rr < 2; rr++) {
                float ov1 = __shfl_xor_sync(~0u, rv1[mt][rr], o);
                int   oi1 = __shfl_xor_sync(~0u, ri1[mt][rr], o);
                float ov2 = __shfl_xor_sync(~0u, rv2[mt][rr], o);
                int   oi2 = __shfl_xor_sync(~0u, ri2[mt][rr], o);
                float ov3 = __shfl_xor_sync(~0u, rv3[mt][rr], o);
                ins2v3(ov1, oi1, rv1[mt][rr], ri1[mt][rr],
                       rv2[mt][rr], ri2[mt][rr], rv3[mt][rr]);
                ins2v3(ov2, oi2, rv1[mt][rr], ri1[mt][rr],
                       rv2[mt][rr], ri2[mt][rr], rv3[mt][rr]);
                rv3[mt][rr] = fminf(rv3[mt][rr], ov3);
            }
    }
    if (p == 0) {
#pragma unroll
        for (int mt = 0; mt < 2; mt++)
#pragma unroll
            for (int rr = 0; rr < 2; rr++) {
                int tok = mw * 32 + mt * 16 + rr * 8 + g;
                stg[tok * 2 + nw] = make_float4(rv1[mt][rr], __int_as_float(ri1[mt][rr]),
                                                rv2[mt][rr], __int_as_float(ri2[mt][rr]));
                sv3[tok * 2 + nw] = rv3[mt][rr];
            }
    }
    __syncthreads();

    // ---- per-token final merge + flag ----
    if (t < 128) {
        float4 a0 = stg[t * 2 + 0];
        float4 b0 = stg[t * 2 + 1];
        float fv1 = a0.x, fv2 = a0.z, fv3 = sv3[t * 2 + 0];
        int   fi1 = __float_as_int(a0.y), fi2 = __float_as_int(a0.w);
        ins2v3(b0.x, __float_as_int(b0.y), fv1, fi1, fv2, fi2, fv3);
        ins2v3(b0.z, __float_as_int(b0.w), fv1, fi1, fv2, fi2, fv3);
        fv3 = fminf(fv3, sv3[t * 2 + 1]);
        sRow[t] = fi1;
        if (fv3 - fv1 < MARGIN) {
            int s = atomicAdd(&sCnt[1], 1);
            sDP[s] = t;
        } else if (fv2 - fv1 < MARGIN) {
            int s = atomicAdd(&sCnt[0], 1);
            sPT[s] = t;
            sPC[s] = make_int2(fi1, fi2);
        }
    }
    __syncthreads();

    // ---- in-block exact fp32 pair rescore (one warp per flagged token) ----
    const int pairCnt = sCnt[0], deepCnt = sCnt[1];
    for (int i = w; i < pairCnt; i += 8) {
        int tok = sPT[i]; int2 cc = sPC[i];
        const float* zp = zb + tok;
        const float* p1 = cb + cc.x * D;
        const float* p2 = cb + cc.y * D;
        float zz = 0.f, d1 = 0.f, d2 = 0.f;
#pragma unroll
        for (int d = lane; d < D; d += 32) {
            float ze = zp[d * HW];
            zz = fmaf(ze, ze, zz);
            d1 = fmaf(ze, __ldg(p1 + d), d1);
            d2 = fmaf(ze, __ldg(p2 + d), d2);
        }
#pragma unroll
        for (int o = 16; o; o >>= 1) {
            zz += __shfl_xor_sync(~0u, zz, o);
            d1 += __shfl_xor_sync(~0u, d1, o);
            d2 += __shfl_xor_sync(~0u, d2, o);
        }
        if (lane == 0) {
            float D1 = __fadd_rn(__fsub_rn(zz, __fmul_rn(2.f, d1)), g_cnorm[cc.x]);
            float D2 = __fadd_rn(__fsub_rn(zz, __fmul_rn(2.f, d2)), g_cnorm[cc.y]);
            sRow[tok] = better(D2, cc.y, D1, cc.x) ? cc.y : cc.x;
        }
    }
    __syncthreads();

    // ---- in-block exact fp32 full scan for deep-doubt (rare) ----
    float* sz = (float*)(sm + OFF_B);
    for (int e = 0; e < deepCnt; e++) {
        int tok = sDP[e];
        sz[t] = zb[tok + t * HW];
        if (t == 0) *sBest = ~0ull;
        __syncthreads();
        const float4* szp = (const float4*)sz;
        float bv = 3.4e38f; int bi = 0;
#pragma unroll
        for (int j = 0; j < 4; j++) {
            int c = t + j * 256;
            const float4* row = (const float4*)(cb + c * D);
            float dsum = 0.f;
#pragma unroll 8
            for (int q = 0; q < 64; q++) {
                float4 zv = szp[q];
                float4 rv = __ldg(row + q);
                dsum = fmaf(zv.x, rv.x, dsum);
                dsum = fmaf(zv.y, rv.y, dsum);
                dsum = fmaf(zv.z, rv.z, dsum);
                dsum = fmaf(zv.w, rv.w, dsum);
            }
            float v = fmaf(-2.f, dsum, g_cnorm[c]);
            if (v < bv) { bv = v; bi = c; }
        }
        unsigned long long key = ((unsigned long long)fkey(bv) << 32) | (uint32_t)bi;
        atomicMin(sBest, key);
        __syncthreads();
        if (t == 0) sRow[tok] = (int)(*sBest & 0xffffffffu);
        __syncthreads();
    }

    // ---- outputs: indices, z_q_st via smem-staged coalesced gather, loss ----
    if (t < 128) out[IDX_OFF + n0 + t] = (float)sRow[t];

    float* stage = (float*)(sm + OFF_A);   // [32][260] f32 (reuses A panel space)
    float* outz = out + b * (D * HW) + hw0;
    float lsum = 0.f;
    for (int g4 = 0; g4 < 4; g4++) {
        const int i0 = g4 * 32;
        __syncthreads();     // stage safe to overwrite
#pragma unroll
        for (int j = 0; j < 8; j++) {
            int idx = j * 256 + t;
            int tl = idx >> 6, f4 = idx & 63;
            float4 v = __ldg((const float4*)(cb + sRow[i0 + tl] * D) + f4);
            *(float4*)(stage + tl * 260 + f4 * 4) = v;
        }
        __syncthreads();
#pragma unroll 8
        for (int j = 0; j < 32; j++) {
            int l = j * 256 + t;
            int d = l >> 5, i = l & 31;
            float ze = zb[d * HW + i0 + i];
            float zq = stage[i * 260 + d];
            float diff = zq - ze;
            outz[d * HW + i0 + i] = ze + diff;
            lsum = fmaf(diff, diff, lsum);
        }
    }
#pragma unroll
    for (int o = 16; o; o >>= 1) lsum += __shfl_xor_sync(~0u, lsum, o);
    if (lane == 0) wsum[w] = lsum;
    __syncthreads();
    if (t == 0) {
        float s = 0.f;
#pragma unroll
        for (int ww = 0; ww < 8; ww++) s += wsum[ww];
        g_partial[blockIdx.x] = s;
    }
}

// ---------------- Kernel 2: final loss ----------------
__global__ void finalize_kernel(float* __restrict__ out) {
    float s = 0.f;
    for (int i = 0; i < NBLK; i++) s += g_partial[i];
    float mean = s / 8388608.f;
    out[LOSS_OFF] = mean + 0.25f * mean;
}

// ---------------------------------------------------------------------------
extern "C" void kernel_launch(void* const* d_in, const int* in_sizes, int n_in,
                              void* d_out, int out_size) {
    const float* z  = (const float*)d_in[0];
    const float* cb = (const float*)d_in[1];
    float* out = (float*)d_out;

    cudaFuncSetAttribute(vq_main, cudaFuncAttributeMaxDynamicSharedMemorySize, SMEM_SZ);

    prepcn_kernel<<<K, 256>>>(cb);
    vq_main<<<NBLK, 256, SMEM_SZ>>>(z, cb, out);
    finalize_kernel<<<1, 1>>>(out);
}